// round 5
// baseline (speedup 1.0000x reference)
#include <cuda_runtime.h>
#include <cstdint>

#define B 32
#define NN 20000
#define F 64
#define JO 64
#define E 16
#define NCHUNK 10
#define CHUNK 2000
#define NPB 136

// Scratch (static device arrays — no allocation)
__device__ float g_zpart[B * NCHUNK * F * E];   // [b][chunk][i*16+f]  1.31 MB
__device__ float g_z[B * F * E];                // [b][i][f]
__device__ float g_w[B * JO * E];               // [b][j][e]

typedef unsigned long long u64;

static __device__ __forceinline__ u64 ffma2(u64 a, u64 b, u64 c) {
    u64 d;
    asm("fma.rn.f32x2 %0, %1, %2, %3;" : "=l"(d) : "l"(a), "l"(b), "l"(c));
    return d;
}
static __device__ __forceinline__ u64 pack2(float lo, float hi) {
    u64 r; asm("mov.b64 %0, {%1, %2};" : "=l"(r) : "f"(lo), "f"(hi)); return r;
}
static __device__ __forceinline__ float2 unpack2(u64 v) {
    float2 f; asm("mov.b64 {%0, %1}, %2;" : "=f"(f.x), "=f"(f.y) : "l"(v)); return f;
}

// ---------------------------------------------------------------------------
// Kernel 1: partial z[b,i,f] = sum_m V[m,f] * x[b,m,i] over one m-chunk.
// grid (NCHUNK, B), 256 threads: ms = t>>4 (m stripe), ig = t&15 (i quad).
// Each thread: 4 i x 16 f accumulators as 32 f32x2 (f-paired).
// 5 m-rows per iteration (batched LDG.128) to keep ~40KB/SM x in flight.
// ---------------------------------------------------------------------------
__global__ void __launch_bounds__(256, 2)
k1_project(const float* __restrict__ x, const float* __restrict__ V) {
    const int c  = blockIdx.x;
    const int b  = blockIdx.y;
    const int t  = threadIdx.x;
    const int ms = t >> 4;      // 0..15
    const int ig = t & 15;      // i = 4*ig

    u64 acc[4][8];
#pragma unroll
    for (int ii = 0; ii < 4; ++ii)
#pragma unroll
        for (int fp = 0; fp < 8; ++fp) acc[ii][fp] = 0ULL;

    const int mbase = c * CHUNK;
    const float* xp = x + ((size_t)b * NN + mbase + ms) * F + ig * 4;
    const float* Vp = V + (size_t)(mbase + ms) * E;

    for (int it = 0; it < 25; ++it) {           // 25 iters * 80 m = 2000 m
        float4 xa[5];
#pragma unroll
        for (int s = 0; s < 5; ++s)
            xa[s] = *reinterpret_cast<const float4*>(xp + (size_t)(it * 80 + s * 16) * F);
#pragma unroll
        for (int s = 0; s < 5; ++s) {
            const float* vr = Vp + (size_t)(it * 80 + s * 16) * E;
            u64 v2[8];
#pragma unroll
            for (int q = 0; q < 4; ++q) {
                ulonglong2 vq = *reinterpret_cast<const ulonglong2*>(vr + q * 4);
                v2[q * 2] = vq.x; v2[q * 2 + 1] = vq.y;
            }
            u64 a0 = pack2(xa[s].x, xa[s].x);
            u64 a1 = pack2(xa[s].y, xa[s].y);
            u64 a2 = pack2(xa[s].z, xa[s].z);
            u64 a3 = pack2(xa[s].w, xa[s].w);
#pragma unroll
            for (int fp = 0; fp < 8; ++fp) {
                acc[0][fp] = ffma2(a0, v2[fp], acc[0][fp]);
                acc[1][fp] = ffma2(a1, v2[fp], acc[1][fp]);
                acc[2][fp] = ffma2(a2, v2[fp], acc[2][fp]);
                acc[3][fp] = ffma2(a3, v2[fp], acc[3][fp]);
            }
        }
    }

    // Reduce the 16 ms replicas: shfl xor 16 (pairs ms within warp), then smem.
    __shared__ float sred[8][16][64];   // [warp][ig][ii*16+f]   32 KB
    const int warp = t >> 5, lane = t & 31;
#pragma unroll
    for (int ii = 0; ii < 4; ++ii)
#pragma unroll
        for (int fp = 0; fp < 8; ++fp) {
            float2 f = unpack2(acc[ii][fp]);
            f.x += __shfl_xor_sync(0xffffffffu, f.x, 16);
            f.y += __shfl_xor_sync(0xffffffffu, f.y, 16);
            if (lane < 16) {
                sred[warp][lane][ii * 16 + fp * 2]     = f.x;
                sred[warp][lane][ii * 16 + fp * 2 + 1] = f.y;
            }
        }
    __syncthreads();

    float* zp = g_zpart + (size_t)(b * NCHUNK + c) * (F * E);
#pragma unroll
    for (int r = 0; r < 4; ++r) {
        int idx = t + r * 256;              // idx = i*16 + f
        int i = idx >> 4, f = idx & 15;
        float s = 0.f;
#pragma unroll
        for (int w = 0; w < 8; ++w) s += sred[w][i >> 2][(i & 3) * 16 + f];
        zp[idx] = s;
    }
}

// ---------------------------------------------------------------------------
// Kernel 2a: fold the NCHUNK partials -> z.  grid 32, block 1024.
// ---------------------------------------------------------------------------
__global__ void k2a_reduce() {
    const int b = blockIdx.x, t = threadIdx.x;
    float s = 0.f;
#pragma unroll
    for (int c = 0; c < NCHUNK; ++c)
        s += g_zpart[(size_t)(b * NCHUNK + c) * 1024 + t];
    g_z[(size_t)b * 1024 + t] = s;
}

// ---------------------------------------------------------------------------
// Kernel 2b: w[b,j,e] = sum_{i,f} G[j,i,e,f] * z[b,i,f].
// grid 64 (j), 256 threads: i0 = t>>2, eq = t&3 (e quad).
// G slice cached in registers ONCE per block (read G exactly once total).
// Per-b: 8 FFMA2 chains, shfl-xor reduce over i0 within warp, smem over warps.
// ---------------------------------------------------------------------------
__global__ void __launch_bounds__(256)
k2b_filter(const float* __restrict__ G) {
    const int j  = blockIdx.x;
    const int t  = threadIdx.x;
    const int i0 = t >> 2, eq = t & 3;
    const int warp = t >> 5, lane = t & 31;

    u64 g2[4][8];     // [e'][f-pair]
    const float* Gp = G + (size_t)((j * 64 + i0) * 16 + eq * 4) * 16;
#pragma unroll
    for (int ep = 0; ep < 4; ++ep)
#pragma unroll
        for (int q = 0; q < 4; ++q) {
            ulonglong2 gq = *reinterpret_cast<const ulonglong2*>(Gp + ep * 16 + q * 4);
            g2[ep][q * 2] = gq.x; g2[ep][q * 2 + 1] = gq.y;
        }

    __shared__ __align__(16) float sw[8][32][16];   // [warp][b][e]  16 KB

    for (int b = 0; b < B; ++b) {
        const float* zp = g_z + (size_t)b * 1024 + i0 * 16;
        u64 z2[8];
#pragma unroll
        for (int q = 0; q < 4; ++q) {
            ulonglong2 zq = *reinterpret_cast<const ulonglong2*>(zp + q * 4);
            z2[q * 2] = zq.x; z2[q * 2 + 1] = zq.y;
        }
        float pv[4];
#pragma unroll
        for (int ep = 0; ep < 4; ++ep) {
            u64 a = 0ULL;
#pragma unroll
            for (int fp = 0; fp < 8; ++fp) a = ffma2(g2[ep][fp], z2[fp], a);
            float2 f = unpack2(a);
            pv[ep] = f.x + f.y;
        }
        // reduce over i0 within warp: lanes with same (lane&3) share e-quad
#pragma unroll
        for (int d = 4; d <= 16; d <<= 1)
#pragma unroll
            for (int ep = 0; ep < 4; ++ep)
                pv[ep] += __shfl_xor_sync(0xffffffffu, pv[ep], d);
        if (lane < 4) {
            float4 q4 = make_float4(pv[0], pv[1], pv[2], pv[3]);
            *reinterpret_cast<float4*>(&sw[warp][b][lane * 4]) = q4;
        }
    }
    __syncthreads();

#pragma unroll
    for (int r = 0; r < 2; ++r) {
        int idx = t + r * 256;                  // 512 outputs = 32b x 16e
        int b = idx >> 4, e = idx & 15;
        float s = 0.f;
#pragma unroll
        for (int w = 0; w < 8; ++w) s += sw[w][b][e];
        g_w[(size_t)(b * JO + j) * E + e] = s;
    }
}

// ---------------------------------------------------------------------------
// Kernel 3: out[b,n,j] = sum_e V[n,e] * w[b,j,e].
// grid 148 node-tiles, 512 threads: j4 = t&15 (4 j's), b = t>>4.
// w[b, 4j's, :] register-resident (64 regs), V tile staged in smem,
// e-paired FFMA2 (both operands natural pairs), STG.128 along j.
// ---------------------------------------------------------------------------
__global__ void __launch_bounds__(512, 1)
k3_expand(const float* __restrict__ V, float* __restrict__ out) {
    const int t    = threadIdx.x;
    const int j4   = t & 15;
    const int b    = t >> 4;
    const int base = blockIdx.x * NPB;
    const int cnt  = min(NPB, NN - base);

    u64 w2[4][8];    // [jj][e-pair]
    const float* wp = g_w + (size_t)(b * JO + j4 * 4) * E;
#pragma unroll
    for (int jj = 0; jj < 4; ++jj)
#pragma unroll
        for (int q = 0; q < 4; ++q) {
            ulonglong2 wq = *reinterpret_cast<const ulonglong2*>(wp + jj * 16 + q * 4);
            w2[jj][q * 2] = wq.x; w2[jj][q * 2 + 1] = wq.y;
        }

    __shared__ __align__(16) float sv[NPB * 16];
    for (int idx = t; idx < cnt * 16; idx += 512)
        sv[idx] = V[(size_t)base * 16 + idx];
    __syncthreads();

    float* op = out + ((size_t)b * NN + base) * 64 + j4 * 4;
    for (int n = 0; n < cnt; ++n) {
        const float* vr = sv + n * 16;
        u64 v2[8];
#pragma unroll
        for (int q = 0; q < 4; ++q) {
            ulonglong2 vq = *reinterpret_cast<const ulonglong2*>(vr + q * 4);
            v2[q * 2] = vq.x; v2[q * 2 + 1] = vq.y;
        }
        u64 a0 = 0ULL, a1 = 0ULL, a2 = 0ULL, a3 = 0ULL;
#pragma unroll
        for (int ep = 0; ep < 8; ++ep) {
            a0 = ffma2(v2[ep], w2[0][ep], a0);
            a1 = ffma2(v2[ep], w2[1][ep], a1);
            a2 = ffma2(v2[ep], w2[2][ep], a2);
            a3 = ffma2(v2[ep], w2[3][ep], a3);
        }
        float2 f0 = unpack2(a0), f1 = unpack2(a1), f2 = unpack2(a2), f3 = unpack2(a3);
        float4 r = make_float4(f0.x + f0.y, f1.x + f1.y, f2.x + f2.y, f3.x + f3.y);
        *reinterpret_cast<float4*>(op + (size_t)n * 64) = r;
    }
}

// ---------------------------------------------------------------------------
extern "C" void kernel_launch(void* const* d_in, const int* in_sizes, int n_in,
                              void* d_out, int out_size) {
    // Identify inputs by element count (robust to ordering):
    // x: 32*20000*64 = 40,960,000 ; V: 20000*16 = 320,000 ; G: 64*64*16*16 = 1,048,576
    const float* x = nullptr; const float* V = nullptr; const float* G = nullptr;
    for (int i = 0; i < n_in; ++i) {
        if      (in_sizes[i] == B * NN * F)      x = (const float*)d_in[i];
        else if (in_sizes[i] == NN * E)          V = (const float*)d_in[i];
        else if (in_sizes[i] == JO * F * E * E)  G = (const float*)d_in[i];
    }
    float* out = (float*)d_out;

    dim3 g1(NCHUNK, B);
    k1_project<<<g1, 256>>>(x, V);
    k2a_reduce<<<B, 1024>>>();
    k2b_filter<<<JO, 256>>>(G);
    k3_expand<<<(NN + NPB - 1) / NPB, 512>>>(V, out);
}

// round 7
// speedup vs baseline: 1.1229x; 1.1229x over previous
#include <cuda_runtime.h>
#include <cstdint>

#define B 32
#define NN 20000
#define F 64
#define JO 64
#define E 16
#define NCHUNK 100
#define CHUNK 200
#define NPB3 136

// Scratch (static device arrays — no allocation)
__device__ float g_zpart[B * NCHUNK * F * E];   // [b][chunk][i*16+f]  13.1 MB
__device__ float g_z[B * F * E];                // [b][i][f]
__device__ float g_w[B * JO * E];               // [b][j][e]

typedef unsigned long long u64;

static __device__ __forceinline__ u64 ffma2(u64 a, u64 b, u64 c) {
    u64 d;
    asm("fma.rn.f32x2 %0, %1, %2, %3;" : "=l"(d) : "l"(a), "l"(b), "l"(c));
    return d;
}
static __device__ __forceinline__ u64 pack2(float lo, float hi) {
    u64 r; asm("mov.b64 %0, {%1, %2};" : "=l"(r) : "f"(lo), "f"(hi)); return r;
}
static __device__ __forceinline__ float2 unpack2(u64 v) {
    float2 f; asm("mov.b64 {%0, %1}, %2;" : "=f"(f.x), "=f"(f.y) : "l"(v)); return f;
}

// ---------------------------------------------------------------------------
// Kernel 1: partial z[b,i,f] = sum_m V[m,f] * x[b,m,i] over one 200-row chunk.
// grid (NCHUNK, B) = 3200 blocks, 256 threads, occ 4 (32 warps/SM).
// Thread tile: 4 i (x float4) x 4 f (V float4) -> acc = 8 u64 (16 regs).
//   fq = t&3 (f quartet), ig = (t>>2)&15 (i quartet), ms = t>>6 (m stripe 0..3).
// Warp = 4 fq x 8 ig: x LDG.128 dedups 4-way in the wavefront (1x DRAM).
// 8 m-rows per outer iter (2 batched load pairs) -> 32KB x in flight per SM.
// ---------------------------------------------------------------------------
__global__ void __launch_bounds__(256, 4)
k1_project(const float* __restrict__ x, const float* __restrict__ V) {
    const int c  = blockIdx.x;
    const int b  = blockIdx.y;
    const int t  = threadIdx.x;
    const int fq = t & 3;
    const int ig = (t >> 2) & 15;
    const int ms = t >> 6;

    u64 acc[4][2];
#pragma unroll
    for (int ii = 0; ii < 4; ++ii) { acc[ii][0] = 0ULL; acc[ii][1] = 0ULL; }

    const int m0 = c * CHUNK;
    const float* xp = x + ((size_t)b * NN + m0 + ms) * F + ig * 4;
    const float* Vp = V + (size_t)(m0 + ms) * E + fq * 4;

    for (int it = 0; it < CHUNK / 8; ++it) {          // 25 iters x 8 rows
        float4 xa[2]; ulonglong2 vv[2];
#pragma unroll
        for (int s = 0; s < 2; ++s) {
            xa[s] = *reinterpret_cast<const float4*>(xp + (size_t)(it * 8 + s * 4) * F);
            vv[s] = *reinterpret_cast<const ulonglong2*>(Vp + (size_t)(it * 8 + s * 4) * E);
        }
#pragma unroll
        for (int s = 0; s < 2; ++s) {
            u64 a0 = pack2(xa[s].x, xa[s].x);
            u64 a1 = pack2(xa[s].y, xa[s].y);
            u64 a2 = pack2(xa[s].z, xa[s].z);
            u64 a3 = pack2(xa[s].w, xa[s].w);
            acc[0][0] = ffma2(a0, vv[s].x, acc[0][0]);
            acc[0][1] = ffma2(a0, vv[s].y, acc[0][1]);
            acc[1][0] = ffma2(a1, vv[s].x, acc[1][0]);
            acc[1][1] = ffma2(a1, vv[s].y, acc[1][1]);
            acc[2][0] = ffma2(a2, vv[s].x, acc[2][0]);
            acc[2][1] = ffma2(a2, vv[s].y, acc[2][1]);
            acc[3][0] = ffma2(a3, vv[s].x, acc[3][0]);
            acc[3][1] = ffma2(a3, vv[s].y, acc[3][1]);
        }
    }

    // Reduce the 4 ms stripes through smem (once per block, amortized).
    __shared__ float sred[4][64][18];    // pad 18 to break bank conflicts
#pragma unroll
    for (int ii = 0; ii < 4; ++ii) {
        float2 p0 = unpack2(acc[ii][0]);
        float2 p1 = unpack2(acc[ii][1]);
        float* dst = &sred[ms][ig * 4 + ii][fq * 4];
        dst[0] = p0.x; dst[1] = p0.y; dst[2] = p1.x; dst[3] = p1.y;
    }
    __syncthreads();

    float* zp = g_zpart + (size_t)(b * NCHUNK + c) * 1024;
#pragma unroll
    for (int r = 0; r < 4; ++r) {
        int idx = t + r * 256;               // idx = i*16 + f
        int i = idx >> 4, f = idx & 15;
        zp[idx] = sred[0][i][f] + sred[1][i][f] + sred[2][i][f] + sred[3][i][f];
    }
}

// ---------------------------------------------------------------------------
// Kernel 2a: fold NCHUNK partials -> z.  grid (B, 8), block 128 (256 blocks).
// ---------------------------------------------------------------------------
__global__ void k2a_reduce() {
    const int b   = blockIdx.x;
    const int idx = blockIdx.y * 128 + threadIdx.x;   // 0..1023
    const float* p = g_zpart + (size_t)b * NCHUNK * 1024 + idx;
    float s = 0.f;
#pragma unroll
    for (int c = 0; c < NCHUNK; ++c) s += p[(size_t)c * 1024];
    g_z[(size_t)b * 1024 + idx] = s;
}

// ---------------------------------------------------------------------------
// Kernel 2b: w[b,j,e] = sum_{i,f} G[j,i,e,f] * z[b,i,f].
// grid 64 (j), 256 threads; G cached in registers once (read exactly once).
// ---------------------------------------------------------------------------
__global__ void __launch_bounds__(256)
k2b_filter(const float* __restrict__ G) {
    const int j  = blockIdx.x;
    const int t  = threadIdx.x;
    const int i0 = t >> 2, eq = t & 3;
    const int warp = t >> 5, lane = t & 31;

    u64 g2[4][8];     // [e'][f-pair]
    const float* Gp = G + (size_t)((j * 64 + i0) * 16 + eq * 4) * 16;
#pragma unroll
    for (int ep = 0; ep < 4; ++ep)
#pragma unroll
        for (int q = 0; q < 4; ++q) {
            ulonglong2 gq = *reinterpret_cast<const ulonglong2*>(Gp + ep * 16 + q * 4);
            g2[ep][q * 2] = gq.x; g2[ep][q * 2 + 1] = gq.y;
        }

    __shared__ __align__(16) float sw[8][32][16];   // [warp][b][e]  16 KB

    for (int b = 0; b < B; ++b) {
        const float* zp = g_z + (size_t)b * 1024 + i0 * 16;
        u64 z2[8];
#pragma unroll
        for (int q = 0; q < 4; ++q) {
            ulonglong2 zq = *reinterpret_cast<const ulonglong2*>(zp + q * 4);
            z2[q * 2] = zq.x; z2[q * 2 + 1] = zq.y;
        }
        float pv[4];
#pragma unroll
        for (int ep = 0; ep < 4; ++ep) {
            u64 a = 0ULL;
#pragma unroll
            for (int fp = 0; fp < 8; ++fp) a = ffma2(g2[ep][fp], z2[fp], a);
            float2 f = unpack2(a);
            pv[ep] = f.x + f.y;
        }
#pragma unroll
        for (int d = 4; d <= 16; d <<= 1)
#pragma unroll
            for (int ep = 0; ep < 4; ++ep)
                pv[ep] += __shfl_xor_sync(0xffffffffu, pv[ep], d);
        if (lane < 4) {
            float4 q4 = make_float4(pv[0], pv[1], pv[2], pv[3]);
            *reinterpret_cast<float4*>(&sw[warp][b][lane * 4]) = q4;
        }
    }
    __syncthreads();

#pragma unroll
    for (int r = 0; r < 2; ++r) {
        int idx = t + r * 256;                  // 512 outputs = 32b x 16e
        int b = idx >> 4, e = idx & 15;
        float s = 0.f;
#pragma unroll
        for (int w = 0; w < 8; ++w) s += sw[w][b][e];
        g_w[(size_t)(b * JO + j) * E + e] = s;
    }
}

// ---------------------------------------------------------------------------
// Kernel 3: out[b,n,j] = sum_e V[n,e] * w[b,j,e].
// grid (148, 2) = 296 blocks (one wave at occ 2), block 512.
//   j2 = t&31 (2 j's), bh = t>>5, b = blockIdx.y*16 + bh.
// w cache = 16 u64 (32 regs) -> ~55 regs total -> 32 warps/SM.
// V tile in smem (warp-uniform address -> broadcast LDS), STG.64 stores
// (warp writes 256B contiguous along j).
// ---------------------------------------------------------------------------
__global__ void __launch_bounds__(512, 2)
k3_expand(const float* __restrict__ V, float* __restrict__ out) {
    const int t    = threadIdx.x;
    const int j2   = t & 31;
    const int bh   = t >> 5;
    const int b    = blockIdx.y * 16 + bh;
    const int base = blockIdx.x * NPB3;
    const int cnt  = min(NPB3, NN - base);

    u64 w2[2][8];    // [jj][e-pair]
    const float* wp = g_w + (size_t)(b * JO + j2 * 2) * E;
#pragma unroll
    for (int jj = 0; jj < 2; ++jj)
#pragma unroll
        for (int q = 0; q < 4; ++q) {
            ulonglong2 wq = *reinterpret_cast<const ulonglong2*>(wp + jj * 16 + q * 4);
            w2[jj][q * 2] = wq.x; w2[jj][q * 2 + 1] = wq.y;
        }

    __shared__ __align__(16) float sv[NPB3 * 16];
    for (int idx = t; idx < cnt * 16; idx += 512)
        sv[idx] = V[(size_t)base * 16 + idx];
    __syncthreads();

    float* op = out + ((size_t)b * NN + base) * 64 + j2 * 2;
    for (int n = 0; n < cnt; ++n) {
        const ulonglong2* vr = reinterpret_cast<const ulonglong2*>(sv + n * 16);
        u64 a0 = 0ULL, a1 = 0ULL;
#pragma unroll
        for (int q = 0; q < 4; ++q) {
            ulonglong2 vq = vr[q];
            a0 = ffma2(vq.x, w2[0][q * 2],     a0);
            a0 = ffma2(vq.y, w2[0][q * 2 + 1], a0);
            a1 = ffma2(vq.x, w2[1][q * 2],     a1);
            a1 = ffma2(vq.y, w2[1][q * 2 + 1], a1);
        }
        float2 f0 = unpack2(a0), f1 = unpack2(a1);
        float2 r = make_float2(f0.x + f0.y, f1.x + f1.y);
        *reinterpret_cast<float2*>(op + (size_t)n * 64) = r;
    }
}

// ---------------------------------------------------------------------------
extern "C" void kernel_launch(void* const* d_in, const int* in_sizes, int n_in,
                              void* d_out, int out_size) {
    const float* x = nullptr; const float* V = nullptr; const float* G = nullptr;
    for (int i = 0; i < n_in; ++i) {
        if      (in_sizes[i] == B * NN * F)      x = (const float*)d_in[i];
        else if (in_sizes[i] == NN * E)          V = (const float*)d_in[i];
        else if (in_sizes[i] == JO * F * E * E)  G = (const float*)d_in[i];
    }
    float* out = (float*)d_out;

    dim3 g1(NCHUNK, B);
    k1_project<<<g1, 256>>>(x, V);
    dim3 g2a(B, 8);
    k2a_reduce<<<g2a, 128>>>();
    k2b_filter<<<JO, 256>>>(G);
    dim3 g3((NN + NPB3 - 1) / NPB3, 2);
    k3_expand<<<g3, 512>>>(V, out);
}

// round 8
// speedup vs baseline: 1.1499x; 1.0240x over previous
#include <cuda_runtime.h>
#include <cstdint>

#define B 32
#define NN 20000
#define F 64
#define JO 64
#define E 16
#define NCHUNK 125
#define CHUNK 160
#define NPB3 136

// Scratch (static device arrays — no allocation)
__device__ float g_zpart[B * NCHUNK * F * E];   // [b][chunk][i*16+f]  16.4 MB
__device__ float g_z[B * F * E];                // [b][i][f]
__device__ float g_w[B * JO * E];               // [b][j][e]

typedef unsigned long long u64;

static __device__ __forceinline__ u64 ffma2(u64 a, u64 b, u64 c) {
    u64 d;
    asm("fma.rn.f32x2 %0, %1, %2, %3;" : "=l"(d) : "l"(a), "l"(b), "l"(c));
    return d;
}
static __device__ __forceinline__ u64 pack2(float lo, float hi) {
    u64 r; asm("mov.b64 %0, {%1, %2};" : "=l"(r) : "f"(lo), "f"(hi)); return r;
}
static __device__ __forceinline__ float2 unpack2(u64 v) {
    float2 f; asm("mov.b64 {%0, %1}, %2;" : "=f"(f.x), "=f"(f.y) : "l"(v)); return f;
}

// ---------------------------------------------------------------------------
// Kernel 1: partial z[b,i,f] = sum_m V[m,f] * x[b,m,i] over one 160-row chunk.
// grid (125, 32) = 4000 blocks, 256 threads, occ 4 (32 warps/SM).
// Thread tile: 4 i x 4 f -> acc = 8 u64 (16 regs).
//   fq = t&3, ig = (t>>2)&15, ms = t>>6. Warp: x LDG.128 dedups 4-way.
// MLP fix vs R5: 4 x-rows batched per iteration -> 512 B/warp -> ~16 KB x in
// flight per SM (Little's law needs ~20 KB at 6.5 TB/s, 900cy DRAM).
// ---------------------------------------------------------------------------
__global__ void __launch_bounds__(256, 4)
k1_project(const float* __restrict__ x, const float* __restrict__ V) {
    const int c  = blockIdx.x;
    const int b  = blockIdx.y;
    const int t  = threadIdx.x;
    const int fq = t & 3;
    const int ig = (t >> 2) & 15;
    const int ms = t >> 6;

    u64 acc[4][2];
#pragma unroll
    for (int ii = 0; ii < 4; ++ii) { acc[ii][0] = 0ULL; acc[ii][1] = 0ULL; }

    const int m0 = c * CHUNK;
    const float* xp = x + ((size_t)b * NN + m0 + ms) * F + ig * 4;
    const float* Vp = V + (size_t)(m0 + ms) * E + fq * 4;

    for (int it = 0; it < 10; ++it) {            // 10 iters x 16 rows = 160
        float4 xa[4]; ulonglong2 vv[4];
#pragma unroll
        for (int s = 0; s < 4; ++s) {
            const int r = (it * 4 + s) * 4;      // thread row = ms + r
            xa[s] = *reinterpret_cast<const float4*>(xp + r * F);
            vv[s] = *reinterpret_cast<const ulonglong2*>(Vp + r * E);
        }
#pragma unroll
        for (int s = 0; s < 4; ++s) {
            u64 a0 = pack2(xa[s].x, xa[s].x);
            u64 a1 = pack2(xa[s].y, xa[s].y);
            u64 a2 = pack2(xa[s].z, xa[s].z);
            u64 a3 = pack2(xa[s].w, xa[s].w);
            acc[0][0] = ffma2(a0, vv[s].x, acc[0][0]);
            acc[0][1] = ffma2(a0, vv[s].y, acc[0][1]);
            acc[1][0] = ffma2(a1, vv[s].x, acc[1][0]);
            acc[1][1] = ffma2(a1, vv[s].y, acc[1][1]);
            acc[2][0] = ffma2(a2, vv[s].x, acc[2][0]);
            acc[2][1] = ffma2(a2, vv[s].y, acc[2][1]);
            acc[3][0] = ffma2(a3, vv[s].x, acc[3][0]);
            acc[3][1] = ffma2(a3, vv[s].y, acc[3][1]);
        }
    }

    // Reduce the 4 ms stripes through smem (once per block, amortized).
    __shared__ float sred[4][64][18];    // pad 18 to break bank conflicts
#pragma unroll
    for (int ii = 0; ii < 4; ++ii) {
        float2 p0 = unpack2(acc[ii][0]);
        float2 p1 = unpack2(acc[ii][1]);
        float* dst = &sred[ms][ig * 4 + ii][fq * 4];
        dst[0] = p0.x; dst[1] = p0.y; dst[2] = p1.x; dst[3] = p1.y;
    }
    __syncthreads();

    float* zp = g_zpart + (size_t)(b * NCHUNK + c) * 1024;
#pragma unroll
    for (int r = 0; r < 4; ++r) {
        int idx = t + r * 256;               // idx = i*16 + f
        int i = idx >> 4, f = idx & 15;
        zp[idx] = sred[0][i][f] + sred[1][i][f] + sred[2][i][f] + sred[3][i][f];
    }
}

// ---------------------------------------------------------------------------
// Kernel 2a: fold NCHUNK partials -> z.  grid (B, 8), block 128 (256 blocks).
// ---------------------------------------------------------------------------
__global__ void k2a_reduce() {
    const int b   = blockIdx.x;
    const int idx = blockIdx.y * 128 + threadIdx.x;   // 0..1023
    const float* p = g_zpart + (size_t)b * NCHUNK * 1024 + idx;
    float s = 0.f;
#pragma unroll 25
    for (int c = 0; c < NCHUNK; ++c) s += p[(size_t)c * 1024];
    g_z[(size_t)b * 1024 + idx] = s;
}

// ---------------------------------------------------------------------------
// Kernel 2b: w[b,j,e] = sum_{i,f} G[j,i,e,f] * z[b,i,f].
// grid 64 (j), 256 threads; G cached in registers once (read exactly once).
// ---------------------------------------------------------------------------
__global__ void __launch_bounds__(256)
k2b_filter(const float* __restrict__ G) {
    const int j  = blockIdx.x;
    const int t  = threadIdx.x;
    const int i0 = t >> 2, eq = t & 3;
    const int warp = t >> 5, lane = t & 31;

    u64 g2[4][8];     // [e'][f-pair]
    const float* Gp = G + (size_t)((j * 64 + i0) * 16 + eq * 4) * 16;
#pragma unroll
    for (int ep = 0; ep < 4; ++ep)
#pragma unroll
        for (int q = 0; q < 4; ++q) {
            ulonglong2 gq = *reinterpret_cast<const ulonglong2*>(Gp + ep * 16 + q * 4);
            g2[ep][q * 2] = gq.x; g2[ep][q * 2 + 1] = gq.y;
        }

    __shared__ __align__(16) float sw[8][32][16];   // [warp][b][e]  16 KB

    for (int b = 0; b < B; ++b) {
        const float* zp = g_z + (size_t)b * 1024 + i0 * 16;
        u64 z2[8];
#pragma unroll
        for (int q = 0; q < 4; ++q) {
            ulonglong2 zq = *reinterpret_cast<const ulonglong2*>(zp + q * 4);
            z2[q * 2] = zq.x; z2[q * 2 + 1] = zq.y;
        }
        float pv[4];
#pragma unroll
        for (int ep = 0; ep < 4; ++ep) {
            u64 a = 0ULL;
#pragma unroll
            for (int fp = 0; fp < 8; ++fp) a = ffma2(g2[ep][fp], z2[fp], a);
            float2 f = unpack2(a);
            pv[ep] = f.x + f.y;
        }
#pragma unroll
        for (int d = 4; d <= 16; d <<= 1)
#pragma unroll
            for (int ep = 0; ep < 4; ++ep)
                pv[ep] += __shfl_xor_sync(0xffffffffu, pv[ep], d);
        if (lane < 4) {
            float4 q4 = make_float4(pv[0], pv[1], pv[2], pv[3]);
            *reinterpret_cast<float4*>(&sw[warp][b][lane * 4]) = q4;
        }
    }
    __syncthreads();

#pragma unroll
    for (int r = 0; r < 2; ++r) {
        int idx = t + r * 256;                  // 512 outputs = 32b x 16e
        int b = idx >> 4, e = idx & 15;
        float s = 0.f;
#pragma unroll
        for (int w = 0; w < 8; ++w) s += sw[w][b][e];
        g_w[(size_t)(b * JO + j) * E + e] = s;
    }
}

// ---------------------------------------------------------------------------
// Kernel 3: out[b,n,j] = sum_e V[n,e] * w[b,j,e].
// grid (148, 2) = 296 blocks, block 256: j4 = t&15 (4 j's), bh = t>>4,
// b = blockIdx.y*16 + bh. 2 blocks/SM (regs ~96 < 128).
// 4-j register tile minimizes L1 wavefronts per output row (4 vs 6 for 2-j):
// per n per warp: 4 broadcast LDS.128 + 4 STG.128 wavefronts for 2 rows.
// __stcs streaming stores (write-once output, bias L2 eviction).
// ---------------------------------------------------------------------------
__global__ void __launch_bounds__(256, 2)
k3_expand(const float* __restrict__ V, float* __restrict__ out) {
    const int t    = threadIdx.x;
    const int j4   = t & 15;
    const int bh   = t >> 4;
    const int b    = blockIdx.y * 16 + bh;
    const int base = blockIdx.x * NPB3;
    const int cnt  = min(NPB3, NN - base);

    u64 w2[4][8];    // [jj][e-pair]
    const float* wp = g_w + (size_t)(b * JO + j4 * 4) * E;
#pragma unroll
    for (int jj = 0; jj < 4; ++jj)
#pragma unroll
        for (int q = 0; q < 4; ++q) {
            ulonglong2 wq = *reinterpret_cast<const ulonglong2*>(wp + jj * 16 + q * 4);
            w2[jj][q * 2] = wq.x; w2[jj][q * 2 + 1] = wq.y;
        }

    __shared__ __align__(16) float sv[NPB3 * 16];
    for (int idx = t; idx < cnt * 16; idx += 256)
        sv[idx] = V[(size_t)base * 16 + idx];
    __syncthreads();

    float* op = out + ((size_t)b * NN + base) * 64 + j4 * 4;
    for (int n = 0; n < cnt; ++n) {
        const ulonglong2* vr = reinterpret_cast<const ulonglong2*>(sv + n * 16);
        u64 a0 = 0ULL, a1 = 0ULL, a2 = 0ULL, a3 = 0ULL;
#pragma unroll
        for (int q = 0; q < 4; ++q) {
            ulonglong2 vq = vr[q];
            a0 = ffma2(vq.x, w2[0][q * 2],     a0);
            a0 = ffma2(vq.y, w2[0][q * 2 + 1], a0);
            a1 = ffma2(vq.x, w2[1][q * 2],     a1);
            a1 = ffma2(vq.y, w2[1][q * 2 + 1], a1);
            a2 = ffma2(vq.x, w2[2][q * 2],     a2);
            a2 = ffma2(vq.y, w2[2][q * 2 + 1], a2);
            a3 = ffma2(vq.x, w2[3][q * 2],     a3);
            a3 = ffma2(vq.y, w2[3][q * 2 + 1], a3);
        }
        float2 f0 = unpack2(a0), f1 = unpack2(a1), f2 = unpack2(a2), f3 = unpack2(a3);
        float4 r = make_float4(f0.x + f0.y, f1.x + f1.y, f2.x + f2.y, f3.x + f3.y);
        __stcs(reinterpret_cast<float4*>(op + (size_t)n * 64), r);
    }
}

// ---------------------------------------------------------------------------
extern "C" void kernel_launch(void* const* d_in, const int* in_sizes, int n_in,
                              void* d_out, int out_size) {
    const float* x = nullptr; const float* V = nullptr; const float* G = nullptr;
    for (int i = 0; i < n_in; ++i) {
        if      (in_sizes[i] == B * NN * F)      x = (const float*)d_in[i];
        else if (in_sizes[i] == NN * E)          V = (const float*)d_in[i];
        else if (in_sizes[i] == JO * F * E * E)  G = (const float*)d_in[i];
    }
    float* out = (float*)d_out;

    dim3 g1(NCHUNK, B);
    k1_project<<<g1, 256>>>(x, V);
    dim3 g2a(B, 8);
    k2a_reduce<<<g2a, 128>>>();
    k2b_filter<<<JO, 256>>>(G);
    dim3 g3(148, 2);
    k3_expand<<<g3, 256>>>(V, out);
}